// round 1
// baseline (speedup 1.0000x reference)
#include <cuda_runtime.h>

#define Lg 2048
#define LMASK 2047
#define LSHIFT 11
#define NCELL (Lg * Lg)

#define R_OVER_5 0.5554f      /* 2.777 / 5 */
#define ETA 0.8f
#define ONE_MINUS_ETA 0.2f
#define GAMMA 0.8f
#define INV_K 2.0f            /* 1 / 0.5 */

// 16 MB scratch for the fermi profit matrix (upd), static device array (no alloc).
__device__ float g_upd[NCELL];

// ---------------------------------------------------------------------------
// Kernel A: profit (13-point stencil, fused double plus-conv) + Q update
// ---------------------------------------------------------------------------
__global__ __launch_bounds__(256) void spgg_payoff_qupdate(
    const int* __restrict__ type_tm,      // type_t_minus
    const int* __restrict__ type_t,
    const float4* __restrict__ Q,         // [N] rows of 4 floats
    float4* __restrict__ Q_out,
    float* __restrict__ profit_out)
{
    int i = blockIdx.x * blockDim.x + threadIdx.x;
    if (i >= NCELL) return;

    int row = i >> LSHIFT;
    int col = i & LMASK;

    int rm1 = ((row - 1) & LMASK) << LSHIFT;
    int rp1 = ((row + 1) & LMASK) << LSHIFT;
    int rm2 = ((row - 2) & LMASK) << LSHIFT;
    int rp2 = ((row + 2) & LMASK) << LSHIFT;
    int r0  = row << LSHIFT;

    int cm1 = (col - 1) & LMASK;
    int cp1 = (col + 1) & LMASK;
    int cm2 = (col - 2) & LMASK;
    int cp2 = (col + 2) & LMASK;

    // weights of (plus ∘ plus): center 5; orth dist-1: 2; diagonals: 2; dist-2: 1
    int t00 = __ldg(type_t + r0 + col);
    int orth = __ldg(type_t + r0 + cm1) + __ldg(type_t + r0 + cp1)
             + __ldg(type_t + rm1 + col) + __ldg(type_t + rp1 + col);
    int diag = __ldg(type_t + rm1 + cm1) + __ldg(type_t + rm1 + cp1)
             + __ldg(type_t + rp1 + cm1) + __ldg(type_t + rp1 + cp1);
    int far2 = __ldg(type_t + r0 + cm2) + __ldg(type_t + r0 + cp2)
             + __ldg(type_t + rm2 + col) + __ldg(type_t + rp2 + col);

    int S2 = 5 * t00 + 2 * orth + 2 * diag + far2;
    float profit = (float)S2 * R_OVER_5 - 5.0f * (float)t00;

    // ---- Q update ----
    float4 q = Q[i];                 // (Q00, Q01, Q10, Q11)
    int A = __ldg(type_tm + i);
    int B = t00;

    float maxv = B ? fmaxf(q.z, q.w) : fmaxf(q.x, q.y);
    float old  = B ? (A ? q.w : q.y) : (A ? q.z : q.x);
    float upd  = ONE_MINUS_ETA * old + ETA * (profit + GAMMA * maxv);

    if (A == 0) { if (B == 0) q.x = upd; else q.y = upd; }
    else        { if (B == 0) q.z = upd; else q.w = upd; }

    Q_out[i] = q;
    profit_out[i] = profit;
    g_upd[i] = upd;
}

// ---------------------------------------------------------------------------
// Kernel B: fermi update using selected neighbor only
// ---------------------------------------------------------------------------
__global__ __launch_bounds__(256) void spgg_fermi(
    const int* __restrict__ type_t,
    const int* __restrict__ learn_dir,
    const float* __restrict__ learn_prob,
    float* __restrict__ type_out)
{
    int i = blockIdx.x * blockDim.x + threadIdx.x;
    if (i >= NCELL) return;

    int row = i >> LSHIFT;
    int col = i & LMASK;

    int d = __ldg(learn_dir + i);
    int nrow = row, ncol = col;
    // dir 0: roll(+1, axis=1) -> neighbor (row, col-1)
    // dir 1: roll(-1, axis=1) -> neighbor (row, col+1)
    // dir 2: roll(+1, axis=0) -> neighbor (row-1, col)
    // dir 3: roll(-1, axis=0) -> neighbor (row+1, col)
    if (d == 0)      ncol = (col - 1) & LMASK;
    else if (d == 1) ncol = (col + 1) & LMASK;
    else if (d == 2) nrow = (row - 1) & LMASK;
    else             nrow = (row + 1) & LMASK;
    int ni = (nrow << LSHIFT) | ncol;

    float pm  = g_upd[i];
    float pmn = g_upd[ni];
    float W = 1.0f / (1.0f + expf((pm - pmn) * INV_K));

    int ti = __ldg(type_t + i);
    int tn = __ldg(type_t + ni);
    int out = (__ldg(learn_prob + i) <= W) ? tn : ti;

    type_out[i] = (float)out;
}

// ---------------------------------------------------------------------------
// Launch: output layout = concat(Q_new[4N], type_t1[N], profit[N]) as float32
// ---------------------------------------------------------------------------
extern "C" void kernel_launch(void* const* d_in, const int* in_sizes, int n_in,
                              void* d_out, int out_size)
{
    const int*    type_tm = (const int*)   d_in[0];
    const int*    type_t  = (const int*)   d_in[1];
    const float4* Q       = (const float4*)d_in[2];
    const int*    ldir    = (const int*)   d_in[3];
    const float*  lprob   = (const float*) d_in[4];

    float* out        = (float*)d_out;
    float4* Q_out     = (float4*)out;                 // [0, 4N)
    float* type_out   = out + 4 * (size_t)NCELL;      // [4N, 5N)
    float* profit_out = out + 5 * (size_t)NCELL;      // [5N, 6N)

    const int threads = 256;
    const int blocks  = NCELL / threads;

    spgg_payoff_qupdate<<<blocks, threads>>>(type_tm, type_t, Q, Q_out, profit_out);
    spgg_fermi<<<blocks, threads>>>(type_t, ldir, lprob, type_out);
}

// round 3
// speedup vs baseline: 1.2494x; 1.2494x over previous
#include <cuda_runtime.h>

#define Lg 2048
#define LMASK 2047
#define LSHIFT 11
#define NCELL (Lg * Lg)

#define R_OVER_5 0.5554f      /* 2.777 / 5 */
#define ETA 0.8f
#define ONE_MINUS_ETA 0.2f
#define GAMMA 0.8f
#define INV_K 2.0f            /* 1 / 0.5 */

// 16 MB scratch for the fermi profit matrix (upd), static device array (no alloc).
__device__ float g_upd[NCELL];

// ---------------------------------------------------------------------------
// Kernel A: profit (13-point stencil, fused double plus-conv) + Q update.
// 4 cells per thread; stencil loads done as 11 aligned int4 loads.
// ---------------------------------------------------------------------------
__global__ __launch_bounds__(256) void spgg_payoff_qupdate(
    const int4* __restrict__ tm4,        // type_t_minus as int4
    const int4* __restrict__ t4,         // type_t as int4
    const float4* __restrict__ Q,        // [N] rows of 4 floats
    float4* __restrict__ Q_out,
    float4* __restrict__ prof4)
{
    int i4 = blockIdx.x * blockDim.x + threadIdx.x;   // 0 .. N/4-1
    int row  = i4 >> 9;            // 2048/4 = 512 groups per row
    int colg = (i4 & 511) << 2;    // first column of this 4-cell group

    int b0  = (row << LSHIFT) >> 2;
    int bm1 = (((row - 1) & LMASK) << LSHIFT) >> 2;
    int bp1 = (((row + 1) & LMASK) << LSHIFT) >> 2;
    int bm2 = (((row - 2) & LMASK) << LSHIFT) >> 2;
    int bp2 = (((row + 2) & LMASK) << LSHIFT) >> 2;

    int cL = ((colg - 4) & LMASK) >> 2;
    int cC = colg >> 2;
    int cR = ((colg + 4) & LMASK) >> 2;

    // Batched independent loads (high MLP)
    int4 A0L = __ldg(t4 + b0  + cL), A0C = __ldg(t4 + b0  + cC), A0R = __ldg(t4 + b0  + cR);
    int4 M1L = __ldg(t4 + bm1 + cL), M1C = __ldg(t4 + bm1 + cC), M1R = __ldg(t4 + bm1 + cR);
    int4 P1L = __ldg(t4 + bp1 + cL), P1C = __ldg(t4 + bp1 + cC), P1R = __ldg(t4 + bp1 + cR);
    int4 M2C = __ldg(t4 + bm2 + cC), P2C = __ldg(t4 + bp2 + cC);
    int4 Avec = __ldg(tm4 + i4);

    size_t base = (size_t)i4 << 2;   // cell index of first cell
    float4 q0 = Q[base + 0], q1 = Q[base + 1], q2 = Q[base + 2], q3 = Q[base + 3];

    // Assemble column windows: index k means column colg-4+k
    int v0[12] = {A0L.x, A0L.y, A0L.z, A0L.w, A0C.x, A0C.y, A0C.z, A0C.w, A0R.x, A0R.y, A0R.z, A0R.w};
    int vm[12] = {M1L.x, M1L.y, M1L.z, M1L.w, M1C.x, M1C.y, M1C.z, M1C.w, M1R.x, M1R.y, M1R.z, M1R.w};
    int vp[12] = {P1L.x, P1L.y, P1L.z, P1L.w, P1C.x, P1C.y, P1C.z, P1C.w, P1R.x, P1R.y, P1R.z, P1R.w};
    int u2[4]  = {M2C.x, M2C.y, M2C.z, M2C.w};
    int d2[4]  = {P2C.x, P2C.y, P2C.z, P2C.w};
    int Aarr[4] = {Avec.x, Avec.y, Avec.z, Avec.w};
    float4 qarr[4] = {q0, q1, q2, q3};

    float pr[4], up[4];

    #pragma unroll
    for (int j = 0; j < 4; j++) {
        int k = j + 4;
        int t00  = v0[k];
        int orth = v0[k-1] + v0[k+1] + vm[k] + vp[k];
        int diag = vm[k-1] + vm[k+1] + vp[k-1] + vp[k+1];
        int far  = v0[k-2] + v0[k+2] + u2[j] + d2[j];
        int S2   = 5 * t00 + 2 * (orth + diag) + far;
        float profit = (float)S2 * R_OVER_5 - 5.0f * (float)t00;

        float4 q = qarr[j];
        int A = Aarr[j];
        int B = t00;

        float maxv = B ? fmaxf(q.z, q.w) : fmaxf(q.x, q.y);
        float old  = B ? (A ? q.w : q.y) : (A ? q.z : q.x);
        float upd  = ONE_MINUS_ETA * old + ETA * (profit + GAMMA * maxv);

        if (A == 0) { if (B == 0) q.x = upd; else q.y = upd; }
        else        { if (B == 0) q.z = upd; else q.w = upd; }
        qarr[j] = q;
        pr[j] = profit;
        up[j] = upd;
    }

    Q_out[base + 0] = qarr[0];
    Q_out[base + 1] = qarr[1];
    Q_out[base + 2] = qarr[2];
    Q_out[base + 3] = qarr[3];
    prof4[i4] = make_float4(pr[0], pr[1], pr[2], pr[3]);
    reinterpret_cast<float4*>(g_upd)[i4] = make_float4(up[0], up[1], up[2], up[3]);
}

// ---------------------------------------------------------------------------
// Kernel B: fermi update, 4 cells per thread, gathers batched for MLP
// ---------------------------------------------------------------------------
__global__ __launch_bounds__(256) void spgg_fermi(
    const int* __restrict__ type_t,
    const int4* __restrict__ t4,
    const int4* __restrict__ ld4,
    const float4* __restrict__ lp4,
    float4* __restrict__ type_out)
{
    int i4 = blockIdx.x * blockDim.x + threadIdx.x;
    int row  = i4 >> 9;
    int colg = (i4 & 511) << 2;
    int r0 = row << LSHIFT;

    int4   dir  = __ldg(ld4 + i4);
    float4 prob = __ldg(lp4 + i4);
    int4   tt   = __ldg(t4 + i4);
    float4 uu   = reinterpret_cast<const float4*>(g_upd)[i4];

    int dv[4] = {dir.x, dir.y, dir.z, dir.w};
    int tv[4] = {tt.x, tt.y, tt.z, tt.w};
    float uv[4] = {uu.x, uu.y, uu.z, uu.w};
    float pv[4] = {prob.x, prob.y, prob.z, prob.w};

    // Compute neighbor indices first, then batch the 8 independent gathers.
    int ni[4];
    #pragma unroll
    for (int j = 0; j < 4; j++) {
        int col = colg + j;
        int d = dv[j];
        int nr = r0, nc = col;
        if (d == 0)      nc = (col - 1) & LMASK;
        else if (d == 1) nc = (col + 1) & LMASK;
        else if (d == 2) nr = ((row - 1) & LMASK) << LSHIFT;
        else             nr = ((row + 1) & LMASK) << LSHIFT;
        ni[j] = nr | nc;
    }

    float un[4];
    int   tn[4];
    #pragma unroll
    for (int j = 0; j < 4; j++) un[j] = g_upd[ni[j]];
    #pragma unroll
    for (int j = 0; j < 4; j++) tn[j] = __ldg(type_t + ni[j]);

    float ov[4];
    #pragma unroll
    for (int j = 0; j < 4; j++) {
        float W = 1.0f / (1.0f + __expf((uv[j] - un[j]) * INV_K));
        ov[j] = (float)((pv[j] <= W) ? tn[j] : tv[j]);
    }

    type_out[i4] = make_float4(ov[0], ov[1], ov[2], ov[3]);
}

// ---------------------------------------------------------------------------
// Launch: output layout = concat(Q_new[4N], type_t1[N], profit[N]) as float32
// ---------------------------------------------------------------------------
extern "C" void kernel_launch(void* const* d_in, const int* in_sizes, int n_in,
                              void* d_out, int out_size)
{
    const int4*   tm4   = (const int4*)   d_in[0];
    const int4*   t4    = (const int4*)   d_in[1];
    const float4* Q     = (const float4*) d_in[2];
    const int4*   ld4   = (const int4*)   d_in[3];
    const float4* lp4   = (const float4*) d_in[4];

    float* out        = (float*)d_out;
    float4* Q_out     = (float4*)out;                          // [0, 4N)
    float4* type_out  = (float4*)(out + 4 * (size_t)NCELL);    // [4N, 5N)
    float4* prof4     = (float4*)(out + 5 * (size_t)NCELL);    // [5N, 6N)

    const int threads = 256;
    const int blocks  = (NCELL / 4) / threads;   // 4096

    spgg_payoff_qupdate<<<blocks, threads>>>(tm4, t4, Q, Q_out, prof4);
    spgg_fermi<<<blocks, threads>>>((const int*)d_in[1], t4, ld4, lp4, type_out);
}